// round 13
// baseline (speedup 1.0000x reference)
#include <cuda_runtime.h>
#include <cuda_bf16.h>
#include <math.h>
#include <stdint.h>

// ---------------- problem constants ----------------
#define HIMG   56
#define WSZ    7
#define SSH    3
#define NWIN   64            // 8*8 windows
#define LW     49            // window length
#define HEADS  12
#define DIM    384
#define DIM3   1152
#define DFF    1536
#define BATCH  32
#define LSEQ   (HIMG*HIMG)   // 3136
#define BNW    (BATCH*NWIN)  // 2048
#define MROWS  (BNW*LW)      // 100352
#define HD     32            // head dim

#define W_QKV_E (DIM*DIM3)   // 442368
#define W_ATT_E (DIM*DIM)    // 147456
#define W_FC1_E (DIM*DFF)    // 589824
#define W_FC2_E (DFF*DIM)    // 589824

// ---------------- scratch (static device memory; no allocations) ----------------
__device__ __nv_bfloat16 g_hwb [(size_t)MROWS * DIM];    // LN outputs (A operands)
__device__ __nv_bfloat16 g_qkvb[(size_t)MROWS * DIM3];   // qkv (bf16, gathered by attn)
__device__ __nv_bfloat16 g_attb[(size_t)MROWS * DIM];    // attention output (A operand)
__device__ __nv_bfloat16 g_f1b [(size_t)MROWS * DFF];    // fc1 output (A operand)
__device__ float         g_proj[(size_t)MROWS * DIM];    // attn-proj output (fp32, residual path)
__device__ float         g_x2  [(size_t)MROWS * DIM];    // x + attn branch (fp32)
__device__ __nv_bfloat16 g_wtb [W_QKV_E + W_ATT_E + W_FC1_E + W_FC2_E];  // transposed bf16 weights [N][K]

__device__ __forceinline__ float gelu_f(float v) {
    return 0.5f * v * (1.0f + erff(v * 0.70710678118654752f));
}

__device__ __forceinline__ float blk_sum128(float v, float* red) {
    int lane = threadIdx.x & 31, wid = threadIdx.x >> 5;
#pragma unroll
    for (int o = 16; o; o >>= 1) v += __shfl_xor_sync(0xffffffffu, v, o);
    if (lane == 0) red[wid] = v;
    __syncthreads();
    float t = (lane < 4) ? red[lane] : 0.0f;
#pragma unroll
    for (int o = 2; o; o >>= 1) t += __shfl_xor_sync(0xffffffffu, t, o);
    t = __shfl_sync(0xffffffffu, t, 0);
    __syncthreads();
    return t;
}

// ---------------- weight transpose + bf16 convert: W[K][N] -> WT[N][K] ----------------
__global__ void transpose_bf16(const float* __restrict__ src, __nv_bfloat16* __restrict__ dst,
                               int K, int N) {
    __shared__ float tile[32][33];
    int k0 = blockIdx.y * 32, n0 = blockIdx.x * 32;
    int tx = threadIdx.x, ty = threadIdx.y;   // 32 x 8
#pragma unroll
    for (int i = 0; i < 32; i += 8)
        tile[ty + i][tx] = src[(size_t)(k0 + ty + i) * N + n0 + tx];
    __syncthreads();
#pragma unroll
    for (int i = 0; i < 32; i += 8)
        dst[(size_t)(n0 + ty + i) * K + k0 + tx] = __float2bfloat16(tile[tx][ty + i]);
}

// ---------------- LN + roll + window partition -> bf16 ----------------
__global__ void ln_win_kernel(const float* __restrict__ x, const float* __restrict__ gam,
                              const float* __restrict__ bet, __nv_bfloat16* __restrict__ out) {
    __shared__ float red[32];
    int row = blockIdx.x;
    int b2 = row / LW, l = row - b2 * LW;
    int b = b2 >> 6, w = b2 & 63;
    int r = (w >> 3) * WSZ + l / WSZ;
    int c = (w & 7) * WSZ + l % WSZ;
    int r0 = (r + SSH) % HIMG;
    int c0 = (c + SSH) % HIMG;
    const float* xin = x + ((size_t)b * LSEQ + r0 * HIMG + c0) * DIM;
    int tid = threadIdx.x;
    float v0 = xin[tid], v1 = xin[tid + 128], v2 = xin[tid + 256];
    float mu = blk_sum128(v0 + v1 + v2, red) * (1.0f / (float)DIM);
    float d0 = v0 - mu, d1 = v1 - mu, d2 = v2 - mu;
    float var = blk_sum128(d0 * d0 + d1 * d1 + d2 * d2, red) * (1.0f / (float)DIM);
    float inv = rsqrtf(var + 1e-3f);
    __nv_bfloat16* o = out + (size_t)row * DIM;
    o[tid]       = __float2bfloat16(d0 * inv * gam[tid]       + bet[tid]);
    o[tid + 128] = __float2bfloat16(d1 * inv * gam[tid + 128] + bet[tid + 128]);
    o[tid + 256] = __float2bfloat16(d2 * inv * gam[tid + 256] + bet[tid + 256]);
}

// ---------------- fused: x2 = x + window_reverse(unshift(proj));  hw = bf16(LN(x2)) ----------------
__global__ void res_ln_kernel(const float* __restrict__ x, const float* __restrict__ proj,
                              const float* __restrict__ gam, const float* __restrict__ bet,
                              float* __restrict__ x2, __nv_bfloat16* __restrict__ hw) {
    __shared__ float red[32];
    int pix = blockIdx.x;
    int b = pix / LSEQ, p = pix - b * LSEQ;
    int r0 = p / HIMG, c0 = p - r0 * HIMG;
    int r = (r0 + HIMG - SSH) % HIMG;
    int c = (c0 + HIMG - SSH) % HIMG;
    int row_in = (b * NWIN + (r / WSZ) * 8 + (c / WSZ)) * LW + (r % WSZ) * WSZ + (c % WSZ);
    const float* xp = x + (size_t)pix * DIM;
    const float* pp = proj + (size_t)row_in * DIM;
    int tid = threadIdx.x;
    float v0 = xp[tid] + pp[tid];
    float v1 = xp[tid + 128] + pp[tid + 128];
    float v2 = xp[tid + 256] + pp[tid + 256];
    float* xo = x2 + (size_t)pix * DIM;
    xo[tid] = v0; xo[tid + 128] = v1; xo[tid + 256] = v2;
    float mu = blk_sum128(v0 + v1 + v2, red) * (1.0f / (float)DIM);
    float d0 = v0 - mu, d1 = v1 - mu, d2 = v2 - mu;
    float var = blk_sum128(d0 * d0 + d1 * d1 + d2 * d2, red) * (1.0f / (float)DIM);
    float inv = rsqrtf(var + 1e-3f);
    __nv_bfloat16* o = hw + (size_t)pix * DIM;
    o[tid]       = __float2bfloat16(d0 * inv * gam[tid]       + bet[tid]);
    o[tid + 128] = __float2bfloat16(d1 * inv * gam[tid + 128] + bet[tid + 128]);
    o[tid + 256] = __float2bfloat16(d2 * inv * gam[tid + 256] + bet[tid + 256]);
}

// ================= bf16 tensor-core GEMM (m16n8k16) =================
// A [M][K] bf16 row-major (K-contiguous). Bt [N][K] bf16 (transposed weights, K-contiguous).
// C[M,N] = epi(A @ Bt^T + bias); EPI 0: gelu, EPI 1: + res (fp32).
// 128x128x32 CTA tile, 256 threads = 8 warps (2x4), warp tile 64x32.
// smem rows padded to 40 bf16 (20 words): LDS bank = (gid*20+tig)%32 -> all 32 distinct.
#define BMT 128
#define BNT 128
#define BKT 32
#define RSTRW 20                       // row stride in 32-bit words (40 bf16)
#define TILE_WORDS (128*RSTRW)         // 2560 words per tile buffer
#define SM_WORDS (4*TILE_WORDS)        // A0,A1,B0,B1 = 40960 B

__device__ __forceinline__ void cp_async16(uint32_t saddr, const void* g) {
    asm volatile("cp.async.cg.shared.global [%0], [%1], 16;\n" :: "r"(saddr), "l"(g));
}

template <int EPI, bool OUT_BF16>
__global__ void __launch_bounds__(256, 2)
bf16gemm_kernel(const __nv_bfloat16* __restrict__ A, const __nv_bfloat16* __restrict__ Bt,
                const float* __restrict__ bias, const float* __restrict__ res,
                void* __restrict__ Cout, int M, int N, int K) {
    __shared__ uint32_t smw[SM_WORDS];

    const int t = threadIdx.x;
    const int bm = blockIdx.y * BMT, bn = blockIdx.x * BNT;
    const int lane = t & 31, wid = t >> 5;
    const int wm = (wid & 1) * 64;
    const int wn = (wid >> 1) * 32;
    const int gid = lane >> 2, tig = lane & 3;

    // ---- cp.async slots: tile = 128 rows x 32 k bf16 = 8KB -> 2 x 16B per thread ----
    const __nv_bfloat16* aptr[2];
    const __nv_bfloat16* bptr[2];
    uint32_t asaddr[2], bsaddr[2];
    uint32_t smem_base = (uint32_t)__cvta_generic_to_shared(smw);
#pragma unroll
    for (int i = 0; i < 2; i++) {
        int flat = i * 256 + t;          // 16B-chunk index, 512 per tile
        int row = flat >> 2, c = flat & 3;
        aptr[i] = A  + (size_t)(bm + row) * K + c * 8;
        bptr[i] = Bt + (size_t)(bn + row) * K + c * 8;
        asaddr[i] = smem_base + (row * RSTRW + c * 4) * 4;
        bsaddr[i] = smem_base + (2 * TILE_WORDS + row * RSTRW + c * 4) * 4;
    }

    float acc[4][4][4];
#pragma unroll
    for (int a = 0; a < 4; a++)
#pragma unroll
        for (int b = 0; b < 4; b++)
#pragma unroll
            for (int c = 0; c < 4; c++) acc[a][b][c] = 0.0f;

    const int NIT = K / BKT;
    // prologue -> buffer 0
#pragma unroll
    for (int i = 0; i < 2; i++) cp_async16(asaddr[i], aptr[i]);
#pragma unroll
    for (int i = 0; i < 2; i++) cp_async16(bsaddr[i], bptr[i]);
    asm volatile("cp.async.commit_group;\n");

    for (int it = 0; it < NIT; ++it) {
        const int cur = it & 1;
        if (it + 1 < NIT) {
            const int nb = cur ^ 1;
            const int k0 = (it + 1) * BKT;
#pragma unroll
            for (int i = 0; i < 2; i++)
                cp_async16(asaddr[i] + nb * TILE_WORDS * 4, aptr[i] + k0);
#pragma unroll
            for (int i = 0; i < 2; i++)
                cp_async16(bsaddr[i] + nb * TILE_WORDS * 4, bptr[i] + k0);
        }
        asm volatile("cp.async.commit_group;\n");
        asm volatile("cp.async.wait_group 1;\n");
        __syncthreads();

        const uint32_t* Aw = smw + cur * TILE_WORDS;
        const uint32_t* Bw = smw + 2 * TILE_WORDS + cur * TILE_WORDS;
#pragma unroll
        for (int kw = 0; kw < 16; kw += 8) {    // two k16 steps (words 0..7, 8..15)
            uint32_t ua[4][4], ub[4][2];
#pragma unroll
            for (int mt = 0; mt < 4; mt++) {
                int r = wm + mt * 16 + gid;
                ua[mt][0] = Aw[(r)     * RSTRW + kw + tig];
                ua[mt][1] = Aw[(r + 8) * RSTRW + kw + tig];
                ua[mt][2] = Aw[(r)     * RSTRW + kw + tig + 4];
                ua[mt][3] = Aw[(r + 8) * RSTRW + kw + tig + 4];
            }
#pragma unroll
            for (int nt = 0; nt < 4; nt++) {
                int n = wn + nt * 8 + gid;
                ub[nt][0] = Bw[n * RSTRW + kw + tig];
                ub[nt][1] = Bw[n * RSTRW + kw + tig + 4];
            }
#pragma unroll
            for (int mt = 0; mt < 4; mt++)
#pragma unroll
                for (int nt = 0; nt < 4; nt++) {
                    asm volatile(
                        "mma.sync.aligned.m16n8k16.row.col.f32.bf16.bf16.f32 "
                        "{%0,%1,%2,%3}, {%4,%5,%6,%7}, {%8,%9}, {%0,%1,%2,%3};"
                        : "+f"(acc[mt][nt][0]), "+f"(acc[mt][nt][1]),
                          "+f"(acc[mt][nt][2]), "+f"(acc[mt][nt][3])
                        : "r"(ua[mt][0]), "r"(ua[mt][1]), "r"(ua[mt][2]), "r"(ua[mt][3]),
                          "r"(ub[nt][0]), "r"(ub[nt][1]));
                }
        }
        __syncthreads();
    }

    // ---- epilogue ----
#pragma unroll
    for (int mt = 0; mt < 4; mt++) {
        int r0 = bm + wm + mt * 16 + gid;
#pragma unroll
        for (int nt = 0; nt < 4; nt++) {
            int c0 = bn + wn + nt * 8 + 2 * tig;
            float bia0 = bias[c0], bia1 = bias[c0 + 1];
            float v00 = acc[mt][nt][0] + bia0, v01 = acc[mt][nt][1] + bia1;
            float v10 = acc[mt][nt][2] + bia0, v11 = acc[mt][nt][3] + bia1;
            if (EPI == 0) {
                v00 = gelu_f(v00); v01 = gelu_f(v01);
                v10 = gelu_f(v10); v11 = gelu_f(v11);
            } else {
                const float* rp0 = res + (size_t)r0 * N + c0;
                const float* rp1 = res + (size_t)(r0 + 8) * N + c0;
                v00 += rp0[0]; v01 += rp0[1];
                v10 += rp1[0]; v11 += rp1[1];
            }
            if (OUT_BF16) {
                __nv_bfloat16* Cb = (__nv_bfloat16*)Cout;
                __nv_bfloat162 p0, p1;
                p0.x = __float2bfloat16(v00); p0.y = __float2bfloat16(v01);
                p1.x = __float2bfloat16(v10); p1.y = __float2bfloat16(v11);
                *(__nv_bfloat162*)(Cb + (size_t)r0 * N + c0) = p0;
                *(__nv_bfloat162*)(Cb + (size_t)(r0 + 8) * N + c0) = p1;
            } else {
                float* Cf = (float*)Cout;
                *(float2*)(Cf + (size_t)r0 * N + c0) = make_float2(v00, v01);
                *(float2*)(Cf + (size_t)(r0 + 8) * N + c0) = make_float2(v10, v11);
            }
        }
    }
}

// ---------------- per-(window-batch, head) attention (bf16 in / bf16 out) ----------------
__global__ void attn_kernel(const __nv_bfloat16* __restrict__ qkv,
                            const float* __restrict__ bias_table,
                            __nv_bfloat16* __restrict__ att) {
    int b2 = blockIdx.x;
    int h2 = blockIdx.y;
    __shared__ float qs[LW * HD], ks[LW * HD], vs[LW * HD];
    __shared__ float sc[LW][LW + 1];
    __shared__ int   rid[LW];
    int tid = threadIdx.x;

    // scrambled gather (faithful to the channel-major reshape in the source)
    int fbase = b2 * (HEADS * LW * HD) + h2 * (LW * HD);
    for (int idx = tid; idx < LW * HD; idx += 128) {
        int f = fbase + idx;
        int cc = f / (BNW * LW);
        int rem = f - cc * (BNW * LW);
        int bb = rem / LW;
        int ll = rem - bb * LW;
        const __nv_bfloat16* src = qkv + (size_t)(bb * LW + ll) * DIM3;
        qs[idx] = __bfloat162float(src[cc]);
        ks[idx] = __bfloat162float(src[cc + DIM]);
        vs[idx] = __bfloat162float(src[cc + 2 * DIM]);
    }
    if (tid < LW) {
        int w = b2 & 63;
        int r = (w >> 3) * WSZ + tid / WSZ;
        int c = (w & 7) * WSZ + tid % WSZ;
        int gr = (r < 7) ? 0 : (r < 10) ? 1 : (r >= 53) ? 2 : -1;
        int gc = (c < 7) ? 0 : (c < 10) ? 1 : (c >= 53) ? 2 : -1;
        rid[tid] = (gr < 0 || gc < 0) ? 0 : gr * 3 + gc;
    }
    __syncthreads();

    for (int idx = tid; idx < LW * LW; idx += 128) {
        int l = idx / LW, m = idx - l * LW;
        float s = 0.0f;
#pragma unroll
        for (int e = 0; e < HD; e++) s += qs[l * HD + e] * ks[m * HD + e];
        int ri = 13 * ((m % 7 - l % 7) + (m / 7 - l / 7) + 12);
        s += bias_table[ri * HEADS + h2];
        if (rid[l] != rid[m]) s -= 100.0f;
        sc[l][m] = s;
    }
    __syncthreads();

    if (tid < LW) {
        float mx = -1e30f;
        for (int m = 0; m < LW; m++) mx = fmaxf(mx, sc[tid][m]);
        float sum = 0.0f;
        for (int m = 0; m < LW; m++) { float e = expf(sc[tid][m] - mx); sc[tid][m] = e; sum += e; }
        float inv = 1.0f / sum;
        for (int m = 0; m < LW; m++) sc[tid][m] *= inv;
    }
    __syncthreads();

    for (int idx = tid; idx < LW * HD; idx += 128) {
        int l = idx / HD, e = idx - l * HD;
        float o = 0.0f;
#pragma unroll 7
        for (int m = 0; m < LW; m++) o += sc[l][m] * vs[m * HD + e];
        att[(size_t)(b2 * LW + l) * DIM + h2 * HD + e] = __float2bfloat16(o);
    }
}

// ---------------- launch ----------------
extern "C" void kernel_launch(void* const* d_in, const int* in_sizes, int n_in,
                              void* d_out, int out_size) {
    const float* x          = (const float*)d_in[0];
    const float* gamma      = (const float*)d_in[1];
    const float* beta       = (const float*)d_in[2];
    const float* w_qkv      = (const float*)d_in[3];
    const float* b_qkv      = (const float*)d_in[4];
    const float* bias_table = (const float*)d_in[5];
    const float* w_att      = (const float*)d_in[6];
    const float* b_att      = (const float*)d_in[7];
    const float* w_fc1      = (const float*)d_in[8];
    const float* b_fc1      = (const float*)d_in[9];
    const float* w_fc2      = (const float*)d_in[10];
    const float* b_fc2      = (const float*)d_in[11];
    float* out = (float*)d_out;

    __nv_bfloat16 *hw, *qkv, *att, *f1, *wt;
    float *proj, *x2;
    cudaGetSymbolAddress((void**)&hw,   g_hwb);
    cudaGetSymbolAddress((void**)&qkv,  g_qkvb);
    cudaGetSymbolAddress((void**)&att,  g_attb);
    cudaGetSymbolAddress((void**)&f1,   g_f1b);
    cudaGetSymbolAddress((void**)&proj, g_proj);
    cudaGetSymbolAddress((void**)&x2,   g_x2);
    cudaGetSymbolAddress((void**)&wt,   g_wtb);

    __nv_bfloat16* wq = wt;                                  // [DIM3][DIM]
    __nv_bfloat16* wa = wt + W_QKV_E;                        // [DIM][DIM]
    __nv_bfloat16* w1 = wt + W_QKV_E + W_ATT_E;              // [DFF][DIM]
    __nv_bfloat16* w2 = wt + W_QKV_E + W_ATT_E + W_FC1_E;    // [DIM][DFF]

    dim3 tb(32, 8);
    // 0. transpose + convert weights to bf16 [N][K]
    transpose_bf16<<<dim3(DIM3 / 32, DIM / 32),  tb>>>(w_qkv, wq, DIM, DIM3);
    transpose_bf16<<<dim3(DIM / 32,  DIM / 32),  tb>>>(w_att, wa, DIM, DIM);
    transpose_bf16<<<dim3(DFF / 32,  DIM / 32),  tb>>>(w_fc1, w1, DIM, DFF);
    transpose_bf16<<<dim3(DIM / 32,  DFF / 32),  tb>>>(w_fc2, w2, DFF, DIM);
    // 1. hw = bf16(LN(roll+window(x)))
    ln_win_kernel<<<MROWS, 128>>>(x, gamma, beta, hw);
    // 2. qkv = bf16(gelu(hw @ wq^T + b_qkv))
    bf16gemm_kernel<0, true><<<dim3(DIM3 / BNT, MROWS / BMT), 256>>>(hw, wq, b_qkv, nullptr, qkv, MROWS, DIM3, DIM);
    // 3. att = bf16(windowed attention)
    attn_kernel<<<dim3(BNW, HEADS), 128>>>(qkv, bias_table, att);
    // 4. proj = gelu(att @ wa^T + b_att)  (fp32)
    bf16gemm_kernel<0, false><<<dim3(DIM / BNT, MROWS / BMT), 256>>>(att, wa, b_att, nullptr, proj, MROWS, DIM, DIM);
    // 5+6. x2 = x + reverse(proj); hw = bf16(LN(x2))
    res_ln_kernel<<<BATCH * LSEQ, 128>>>(x, proj, gamma, beta, x2, hw);
    // 7. f1 = bf16(gelu(hw @ w1^T + b_fc1))
    bf16gemm_kernel<0, true><<<dim3(DFF / BNT, MROWS / BMT), 256>>>(hw, w1, b_fc1, nullptr, f1, MROWS, DFF, DIM);
    // 8. out = x2 + f1 @ w2^T + b_fc2  (fp32)
    bf16gemm_kernel<1, false><<<dim3(DIM / BNT, MROWS / BMT), 256>>>(f1, w2, b_fc2, x2, out, MROWS, DIM, DFF);
}

// round 14
// speedup vs baseline: 1.4639x; 1.4639x over previous
#include <cuda_runtime.h>
#include <math.h>
#include <stdint.h>

// ---------------- problem constants ----------------
#define HIMG   56
#define WSZ    7
#define SSH    3
#define NWIN   64            // 8*8 windows
#define LW     49            // window length
#define HEADS  12
#define DIM    384
#define DIM3   1152
#define DFF    1536
#define BATCH  32
#define LSEQ   (HIMG*HIMG)   // 3136
#define BNW    (BATCH*NWIN)  // 2048
#define MROWS  (BNW*LW)      // 100352
#define HD     32            // head dim

#define W_QKV_E (DIM*DIM3)   // 442368
#define W_ATT_E (DIM*DIM)    // 147456
#define W_FC1_E (DIM*DFF)    // 589824
#define W_FC2_E (DFF*DIM)    // 589824

// ---------------- scratch (static device memory; no allocations) ----------------
__device__ float g_hw  [(size_t)MROWS * DIM];
__device__ float g_qkv [(size_t)MROWS * DIM3];   // TRANSPOSED: [DIM3][MROWS]
__device__ float g_att [(size_t)MROWS * DIM];
__device__ float g_proj[(size_t)MROWS * DIM];
__device__ float g_x2  [(size_t)MROWS * DIM];
__device__ float g_f1  [(size_t)MROWS * DFF];
__device__ float g_wt  [W_QKV_E + W_ATT_E + W_FC1_E + W_FC2_E];  // tf32-rounded weights

__device__ __forceinline__ float gelu_f(float v) {
    return 0.5f * v * (1.0f + erff(v * 0.70710678118654752f));
}
__device__ __forceinline__ uint32_t cvt_tf32(float f) {
    uint32_t u;
    asm("cvt.rna.tf32.f32 %0, %1;" : "=r"(u) : "f"(f));
    return u;
}
__device__ __forceinline__ float tf32r(float f) { return __uint_as_float(cvt_tf32(f)); }

__device__ __forceinline__ float blk_sum128(float v, float* red) {
    int lane = threadIdx.x & 31, wid = threadIdx.x >> 5;
#pragma unroll
    for (int o = 16; o; o >>= 1) v += __shfl_xor_sync(0xffffffffu, v, o);
    if (lane == 0) red[wid] = v;
    __syncthreads();
    float t = (lane < 4) ? red[lane] : 0.0f;
#pragma unroll
    for (int o = 2; o; o >>= 1) t += __shfl_xor_sync(0xffffffffu, t, o);
    t = __shfl_sync(0xffffffffu, t, 0);
    __syncthreads();
    return t;
}

// ---------------- weight pre-round to tf32 (vectorized) ----------------
__global__ void round_weights(const float* __restrict__ a, const float* __restrict__ b,
                              const float* __restrict__ c, const float* __restrict__ d,
                              float* __restrict__ o) {
    int i = (blockIdx.x * 256 + threadIdx.x) * 4;
    const int n1 = W_QKV_E, n2 = n1 + W_ATT_E, n3 = n2 + W_FC1_E, n4 = n3 + W_FC2_E;
    if (i >= n4) return;
    const float* src;
    int off;
    if (i < n1)      { src = a; off = i; }
    else if (i < n2) { src = b; off = i - n1; }
    else if (i < n3) { src = c; off = i - n2; }
    else             { src = d; off = i - n3; }
    float4 v = *(const float4*)(src + off);
    v.x = tf32r(v.x); v.y = tf32r(v.y); v.z = tf32r(v.z); v.w = tf32r(v.w);
    *(float4*)(o + i) = v;
}

// ---------------- LN + roll + window partition (output tf32-rounded: feeds GEMM A) ----------------
__global__ void ln_win_kernel(const float* __restrict__ x, const float* __restrict__ gam,
                              const float* __restrict__ bet, float* __restrict__ out) {
    __shared__ float red[32];
    int row = blockIdx.x;
    int b2 = row / LW, l = row - b2 * LW;
    int b = b2 >> 6, w = b2 & 63;
    int r = (w >> 3) * WSZ + l / WSZ;
    int c = (w & 7) * WSZ + l % WSZ;
    int r0 = (r + SSH) % HIMG;
    int c0 = (c + SSH) % HIMG;
    const float* xin = x + ((size_t)b * LSEQ + r0 * HIMG + c0) * DIM;
    int tid = threadIdx.x;
    float v0 = xin[tid], v1 = xin[tid + 128], v2 = xin[tid + 256];
    float mu = blk_sum128(v0 + v1 + v2, red) * (1.0f / (float)DIM);
    float d0 = v0 - mu, d1 = v1 - mu, d2 = v2 - mu;
    float var = blk_sum128(d0 * d0 + d1 * d1 + d2 * d2, red) * (1.0f / (float)DIM);
    float inv = rsqrtf(var + 1e-3f);
    float* o = out + (size_t)row * DIM;
    o[tid]       = tf32r(d0 * inv * gam[tid]       + bet[tid]);
    o[tid + 128] = tf32r(d1 * inv * gam[tid + 128] + bet[tid + 128]);
    o[tid + 256] = tf32r(d2 * inv * gam[tid + 256] + bet[tid + 256]);
}

// ---------------- fused: x2 = x + window_reverse(unshift(proj));  hw = tf32(LN(x2)) ----------------
__global__ void res_ln_kernel(const float* __restrict__ x, const float* __restrict__ proj,
                              const float* __restrict__ gam, const float* __restrict__ bet,
                              float* __restrict__ x2, float* __restrict__ hw) {
    __shared__ float red[32];
    int pix = blockIdx.x;
    int b = pix / LSEQ, p = pix - b * LSEQ;
    int r0 = p / HIMG, c0 = p - r0 * HIMG;
    int r = (r0 + HIMG - SSH) % HIMG;
    int c = (c0 + HIMG - SSH) % HIMG;
    int row_in = (b * NWIN + (r / WSZ) * 8 + (c / WSZ)) * LW + (r % WSZ) * WSZ + (c % WSZ);
    const float* xp = x + (size_t)pix * DIM;
    const float* pp = proj + (size_t)row_in * DIM;
    int tid = threadIdx.x;
    float v0 = xp[tid] + pp[tid];
    float v1 = xp[tid + 128] + pp[tid + 128];
    float v2 = xp[tid + 256] + pp[tid + 256];
    float* xo = x2 + (size_t)pix * DIM;
    xo[tid] = v0; xo[tid + 128] = v1; xo[tid + 256] = v2;
    float mu = blk_sum128(v0 + v1 + v2, red) * (1.0f / (float)DIM);
    float d0 = v0 - mu, d1 = v1 - mu, d2 = v2 - mu;
    float var = blk_sum128(d0 * d0 + d1 * d1 + d2 * d2, red) * (1.0f / (float)DIM);
    float inv = rsqrtf(var + 1e-3f);
    float* o = hw + (size_t)pix * DIM;
    o[tid]       = tf32r(d0 * inv * gam[tid]       + bet[tid]);
    o[tid + 128] = tf32r(d1 * inv * gam[tid + 128] + bet[tid + 128]);
    o[tid + 256] = tf32r(d2 * inv * gam[tid + 256] + bet[tid + 256]);
}

// ================= TF32 tensor-core GEMM =================
// Operands are PRE-ROUNDED to tf32 (bit pattern) — no cvt in the inner loop.
// EPI 0: gelu, store C[M,N].  EPI 1: + res, store C[M,N].
// EPI 2: gelu, store TRANSPOSED C_T[N][M] (smem-staged, coalesced).
// RND: tf32-round stored output (EPI 0/1 path only).
#define BMT 128
#define BNT 128
#define BKT 32
#define ASTR 36
#define BSTR 136
#define AS_ELEMS (BMT*ASTR)   // 4608 floats
#define BS_ELEMS (BKT*BSTR)   // 4352 floats
#define GEMM_SMEM ((2*AS_ELEMS + 2*BS_ELEMS)*4)  // 71680 B  (>= 128*132*4 = 67584 for EPI2 staging)

__device__ __forceinline__ void cp_async16(uint32_t saddr, const float* g) {
    asm volatile("cp.async.cg.shared.global [%0], [%1], 16;\n" :: "r"(saddr), "l"(g));
}

template <int EPI, bool RND>
__global__ void __launch_bounds__(256, 2)
tf32gemm_kernel(const float* __restrict__ A, const float* __restrict__ Bm,
                const float* __restrict__ bias, const float* __restrict__ res,
                float* __restrict__ C, int M, int N, int K) {
    extern __shared__ float sm[];
    float* As = sm;                    // [2][128][36]
    float* Bs = sm + 2 * AS_ELEMS;     // [2][32][136]

    const int t = threadIdx.x;
    const int bm = blockIdx.y * BMT, bn = blockIdx.x * BNT;
    const int lane = t & 31, wid = t >> 5;
    const int wm = (wid & 1) * 64;
    const int wn = (wid >> 1) * 32;
    const int gid = lane >> 2, tig = lane & 3;

    const float* aptr[4];
    uint32_t asm_addr[4];
    uint32_t smem_base = (uint32_t)__cvta_generic_to_shared(sm);
#pragma unroll
    for (int i = 0; i < 4; i++) {
        int flat = (i * 256 + t) * 4;
        int arow = flat >> 5, akk = flat & 31;
        aptr[i] = A + (size_t)(bm + arow) * K + akk;
        asm_addr[i] = smem_base + (arow * ASTR + akk) * 4;
    }
    const float* bptr[4];
    uint32_t bsm_addr[4];
#pragma unroll
    for (int i = 0; i < 4; i++) {
        int flat = (i * 256 + t) * 4;
        int bkk = flat >> 7, bno = flat & 127;
        bptr[i] = Bm + (size_t)bkk * N + bn + bno;
        bsm_addr[i] = smem_base + (2 * AS_ELEMS + bkk * BSTR + bno) * 4;
    }

    float acc[4][4][4];
#pragma unroll
    for (int a = 0; a < 4; a++)
#pragma unroll
        for (int b = 0; b < 4; b++)
#pragma unroll
            for (int c = 0; c < 4; c++) acc[a][b][c] = 0.0f;

    const int NIT = K / BKT;
#pragma unroll
    for (int i = 0; i < 4; i++) cp_async16(asm_addr[i], aptr[i]);
#pragma unroll
    for (int i = 0; i < 4; i++) cp_async16(bsm_addr[i], bptr[i]);
    asm volatile("cp.async.commit_group;\n");

    for (int it = 0; it < NIT; ++it) {
        const int cur = it & 1;
        if (it + 1 < NIT) {
            const int nb = cur ^ 1;
            const int k0 = (it + 1) * BKT;
#pragma unroll
            for (int i = 0; i < 4; i++)
                cp_async16(asm_addr[i] + nb * AS_ELEMS * 4, aptr[i] + k0);
#pragma unroll
            for (int i = 0; i < 4; i++)
                cp_async16(bsm_addr[i] + nb * BS_ELEMS * 4, bptr[i] + (size_t)k0 * N);
        }
        asm volatile("cp.async.commit_group;\n");
        asm volatile("cp.async.wait_group 1;\n");
        __syncthreads();

        const uint32_t* Ac = (const uint32_t*)(As + cur * AS_ELEMS);
        const uint32_t* Bc = (const uint32_t*)(Bs + cur * BS_ELEMS);
#pragma unroll
        for (int k8 = 0; k8 < BKT; k8 += 8) {
            uint32_t ua[4][4], ub[4][2];
#pragma unroll
            for (int mt = 0; mt < 4; mt++) {
                int r = wm + mt * 16 + gid;
                ua[mt][0] = Ac[(r)     * ASTR + k8 + tig];
                ua[mt][1] = Ac[(r + 8) * ASTR + k8 + tig];
                ua[mt][2] = Ac[(r)     * ASTR + k8 + tig + 4];
                ua[mt][3] = Ac[(r + 8) * ASTR + k8 + tig + 4];
            }
#pragma unroll
            for (int nt = 0; nt < 4; nt++) {
                int ncol = wn + nt * 8 + gid;
                ub[nt][0] = Bc[(k8 + tig)     * BSTR + ncol];
                ub[nt][1] = Bc[(k8 + tig + 4) * BSTR + ncol];
            }
#pragma unroll
            for (int mt = 0; mt < 4; mt++)
#pragma unroll
                for (int nt = 0; nt < 4; nt++) {
                    asm volatile(
                        "mma.sync.aligned.m16n8k8.row.col.f32.tf32.tf32.f32 "
                        "{%0,%1,%2,%3}, {%4,%5,%6,%7}, {%8,%9}, {%0,%1,%2,%3};"
                        : "+f"(acc[mt][nt][0]), "+f"(acc[mt][nt][1]),
                          "+f"(acc[mt][nt][2]), "+f"(acc[mt][nt][3])
                        : "r"(ua[mt][0]), "r"(ua[mt][1]), "r"(ua[mt][2]), "r"(ua[mt][3]),
                          "r"(ub[nt][0]), "r"(ub[nt][1]));
                }
        }
        __syncthreads();
    }

    // ---- epilogue ----
    if (EPI == 2) {
        // gelu + transposed store: stage tile in smem [n][m] stride 132, then
        // write C_T[bn+n][bm..bm+127] with coalesced float4s.
        float* st = sm;   // mainloop smem fully consumed (synced after last iter)
#pragma unroll
        for (int mt = 0; mt < 4; mt++) {
            int r0 = wm + mt * 16 + gid;
#pragma unroll
            for (int nt = 0; nt < 4; nt++) {
                int c0 = wn + nt * 8 + 2 * tig;
                float bia0 = bias[bn + c0], bia1 = bias[bn + c0 + 1];
                float v00 = gelu_f(acc[mt][nt][0] + bia0);
                float v01 = gelu_f(acc[mt][nt][1] + bia1);
                float v10 = gelu_f(acc[mt][nt][2] + bia0);
                float v11 = gelu_f(acc[mt][nt][3] + bia1);
                st[(c0)     * 132 + r0]     = v00;
                st[(c0 + 1) * 132 + r0]     = v01;
                st[(c0)     * 132 + r0 + 8] = v10;
                st[(c0 + 1) * 132 + r0 + 8] = v11;
            }
        }
        __syncthreads();
#pragma unroll
        for (int rep = 0; rep < 4; rep++) {
            int n = rep * 32 + (t >> 3);
            int mb = (t & 7) * 4;
#pragma unroll
            for (int k = 0; k < 4; k++) {
                int m = mb + 32 * k;
                float4 v = *(float4*)&st[n * 132 + m];
                *(float4*)(C + (size_t)(bn + n) * M + bm + m) = v;
            }
        }
    } else {
#pragma unroll
        for (int mt = 0; mt < 4; mt++) {
            int r0 = bm + wm + mt * 16 + gid;
#pragma unroll
            for (int nt = 0; nt < 4; nt++) {
                int c0 = bn + wn + nt * 8 + 2 * tig;
                float bia0 = bias[c0], bia1 = bias[c0 + 1];
                float v00 = acc[mt][nt][0] + bia0, v01 = acc[mt][nt][1] + bia1;
                float v10 = acc[mt][nt][2] + bia0, v11 = acc[mt][nt][3] + bia1;
                if (EPI == 0) {
                    v00 = gelu_f(v00); v01 = gelu_f(v01);
                    v10 = gelu_f(v10); v11 = gelu_f(v11);
                } else {
                    const float* rp0 = res + (size_t)r0 * N + c0;
                    const float* rp1 = res + (size_t)(r0 + 8) * N + c0;
                    v00 += rp0[0]; v01 += rp0[1];
                    v10 += rp1[0]; v11 += rp1[1];
                }
                if (RND) {
                    v00 = tf32r(v00); v01 = tf32r(v01);
                    v10 = tf32r(v10); v11 = tf32r(v11);
                }
                float2* o0 = (float2*)(C + (size_t)r0 * N + c0);
                float2* o1 = (float2*)(C + (size_t)(r0 + 8) * N + c0);
                *o0 = make_float2(v00, v01);
                *o1 = make_float2(v10, v11);
            }
        }
    }
}

// ---------------- per-(window-batch, head) attention ----------------
// qkvT layout: [DIM3][MROWS]. For a (b2,h2) block, fbase = (b2*HEADS+h2)*1568 is a
// multiple of 1568; MROWS = 64*1568, so cc = fbase/MROWS is CONSTANT over the block
// and the 1568 gathered elements are CONTIGUOUS in the row index -> coalesced loads.
__global__ void attn_kernel(const float* __restrict__ qkvT,
                            const float* __restrict__ bias_table,
                            float* __restrict__ att) {
    int b2 = blockIdx.x;
    int h2 = blockIdx.y;
    __shared__ float qs[LW * HD], ks[LW * HD], vs[LW * HD];
    __shared__ float sc[LW][LW + 1];
    __shared__ int   rid[LW];
    int tid = threadIdx.x;   // 128
    int lane = tid & 31, wid = tid >> 5;

    int fbase = b2 * (HEADS * LW * HD) + h2 * (LW * HD);
    int cc  = fbase / MROWS;
    int off = fbase - cc * MROWS;
    const float* qrow = qkvT + (size_t)(cc)           * MROWS + off;
    const float* krow = qkvT + (size_t)(cc + DIM)     * MROWS + off;
    const float* vrow = qkvT + (size_t)(cc + 2 * DIM) * MROWS + off;
    for (int idx = tid; idx < LW * HD; idx += 128) {
        qs[idx] = qrow[idx];
        ks[idx] = krow[idx];
        vs[idx] = vrow[idx];
    }
    if (tid < LW) {
        int w = b2 & 63;
        int r = (w >> 3) * WSZ + tid / WSZ;
        int c = (w & 7) * WSZ + tid % WSZ;
        int gr = (r < 7) ? 0 : (r < 10) ? 1 : (r >= 53) ? 2 : -1;
        int gc = (c < 7) ? 0 : (c < 10) ? 1 : (c >= 53) ? 2 : -1;
        rid[tid] = (gr < 0 || gc < 0) ? 0 : gr * 3 + gc;
    }
    __syncthreads();

    for (int idx = tid; idx < LW * LW; idx += 128) {
        int l = idx / LW, m = idx - l * LW;
        float s = 0.0f;
#pragma unroll
        for (int e = 0; e < HD; e++) s += qs[l * HD + e] * ks[m * HD + e];
        int ri = 13 * ((m % 7 - l % 7) + (m / 7 - l / 7) + 12);
        s += bias_table[ri * HEADS + h2];
        if (rid[l] != rid[m]) s -= 100.0f;
        sc[l][m] = s;
    }
    __syncthreads();

    // warp-parallel softmax: each warp owns rows l = wid, wid+4, ...
    for (int l = wid; l < LW; l += 4) {
        float a = (lane < LW) ? sc[l][lane] : -1e30f;
        float b = (lane + 32 < LW) ? sc[l][lane + 32] : -1e30f;
        float mx = fmaxf(a, b);
#pragma unroll
        for (int o = 16; o; o >>= 1) mx = fmaxf(mx, __shfl_xor_sync(0xffffffffu, mx, o));
        float e0 = (lane < LW) ? expf(a - mx) : 0.0f;
        float e1 = (lane + 32 < LW) ? expf(b - mx) : 0.0f;
        float s = e0 + e1;
#pragma unroll
        for (int o = 16; o; o >>= 1) s += __shfl_xor_sync(0xffffffffu, s, o);
        float inv = 1.0f / s;
        if (lane < LW) sc[l][lane] = e0 * inv;
        if (lane + 32 < LW) sc[l][lane + 32] = e1 * inv;
    }
    __syncthreads();

    for (int idx = tid; idx < LW * HD; idx += 128) {
        int l = idx / HD, e = idx - l * HD;
        float o = 0.0f;
#pragma unroll 7
        for (int m = 0; m < LW; m++) o += sc[l][m] * vs[m * HD + e];
        att[(size_t)(b2 * LW + l) * DIM + h2 * HD + e] = tf32r(o);
    }
}

// ---------------- launch ----------------
extern "C" void kernel_launch(void* const* d_in, const int* in_sizes, int n_in,
                              void* d_out, int out_size) {
    const float* x          = (const float*)d_in[0];
    const float* gamma      = (const float*)d_in[1];
    const float* beta       = (const float*)d_in[2];
    const float* w_qkv      = (const float*)d_in[3];
    const float* b_qkv      = (const float*)d_in[4];
    const float* bias_table = (const float*)d_in[5];
    const float* w_att      = (const float*)d_in[6];
    const float* b_att      = (const float*)d_in[7];
    const float* w_fc1      = (const float*)d_in[8];
    const float* b_fc1      = (const float*)d_in[9];
    const float* w_fc2      = (const float*)d_in[10];
    const float* b_fc2      = (const float*)d_in[11];
    float* out = (float*)d_out;

    float *hw, *qkv, *att, *proj, *x2, *f1, *wt;
    cudaGetSymbolAddress((void**)&hw,   g_hw);
    cudaGetSymbolAddress((void**)&qkv,  g_qkv);
    cudaGetSymbolAddress((void**)&att,  g_att);
    cudaGetSymbolAddress((void**)&proj, g_proj);
    cudaGetSymbolAddress((void**)&x2,   g_x2);
    cudaGetSymbolAddress((void**)&f1,   g_f1);
    cudaGetSymbolAddress((void**)&wt,   g_wt);

    const float* wq = wt;
    const float* wa = wt + W_QKV_E;
    const float* w1 = wt + W_QKV_E + W_ATT_E;
    const float* w2 = wt + W_QKV_E + W_ATT_E + W_FC1_E;

    cudaFuncSetAttribute(tf32gemm_kernel<0, false>, cudaFuncAttributeMaxDynamicSharedMemorySize, GEMM_SMEM);
    cudaFuncSetAttribute(tf32gemm_kernel<0, true>,  cudaFuncAttributeMaxDynamicSharedMemorySize, GEMM_SMEM);
    cudaFuncSetAttribute(tf32gemm_kernel<1, false>, cudaFuncAttributeMaxDynamicSharedMemorySize, GEMM_SMEM);
    cudaFuncSetAttribute(tf32gemm_kernel<2, false>, cudaFuncAttributeMaxDynamicSharedMemorySize, GEMM_SMEM);

    // 0. tf32-round all weights once per call
    {
        int total = W_QKV_E + W_ATT_E + W_FC1_E + W_FC2_E;
        round_weights<<<(total / 4 + 255) / 256, 256>>>(w_qkv, w_att, w_fc1, w_fc2, wt);
    }
    // 1. hw = tf32(LN(roll+window(x)))
    ln_win_kernel<<<MROWS, 128>>>(x, gamma, beta, hw);
    // 2. qkvT = gelu(hw @ wq + b_qkv), stored TRANSPOSED [DIM3][MROWS]
    tf32gemm_kernel<2, false><<<dim3(DIM3 / BNT, MROWS / BMT), 256, GEMM_SMEM>>>(hw, wq, b_qkv, nullptr, qkv, MROWS, DIM3, DIM);
    // 3. att = tf32(windowed attention), coalesced gather from qkvT
    attn_kernel<<<dim3(BNW, HEADS), 128>>>(qkv, bias_table, att);
    // 4. proj = gelu(att @ wa + b_att)
    tf32gemm_kernel<0, false><<<dim3(DIM / BNT, MROWS / BMT), 256, GEMM_SMEM>>>(att, wa, b_att, nullptr, proj, MROWS, DIM, DIM);
    // 5+6. x2 = x + reverse(proj); hw = tf32(LN(x2))
    res_ln_kernel<<<BATCH * LSEQ, 128>>>(x, proj, gamma, beta, x2, hw);
    // 7. f1 = tf32(gelu(hw @ w1 + b_fc1))
    tf32gemm_kernel<0, true><<<dim3(DFF / BNT, MROWS / BMT), 256, GEMM_SMEM>>>(hw, w1, b_fc1, nullptr, f1, MROWS, DFF, DIM);
    // 8. out = x2 + f1 @ w2 + b_fc2
    tf32gemm_kernel<1, false><<<dim3(DIM / BNT, MROWS / BMT), 256, GEMM_SMEM>>>(f1, w2, b_fc2, x2, out, MROWS, DIM, DFF);
}

// round 16
// speedup vs baseline: 2.0391x; 1.3930x over previous
#include <cuda_runtime.h>
#include <math.h>
#include <stdint.h>

// ---------------- problem constants ----------------
#define HIMG   56
#define WSZ    7
#define SSH    3
#define NWIN   64            // 8*8 windows
#define LW     49            // window length
#define HEADS  12
#define DIM    384
#define DIM3   1152
#define DFF    1536
#define BATCH  32
#define LSEQ   (HIMG*HIMG)   // 3136
#define BNW    (BATCH*NWIN)  // 2048
#define MROWS  (BNW*LW)      // 100352
#define HD     32            // head dim
#define KSTR   51            // transposed-K smem row stride (odd -> conflict-free both ways)

#define W_QKV_E (DIM*DIM3)   // 442368
#define W_ATT_E (DIM*DIM)    // 147456
#define W_FC1_E (DIM*DFF)    // 589824
#define W_FC2_E (DFF*DIM)    // 589824

// ---------------- scratch (static device memory; no allocations) ----------------
__device__ float g_hw  [(size_t)MROWS * DIM];
__device__ float g_qkv [(size_t)MROWS * DIM3];   // TRANSPOSED: [DIM3][MROWS]
__device__ float g_att [(size_t)MROWS * DIM];
__device__ float g_proj[(size_t)MROWS * DIM];
__device__ float g_x2  [(size_t)MROWS * DIM];
__device__ float g_f1  [(size_t)MROWS * DFF];
__device__ float g_wt  [W_QKV_E + W_ATT_E + W_FC1_E + W_FC2_E];  // tf32-rounded weights

__device__ __forceinline__ float gelu_f(float v) {
    return 0.5f * v * (1.0f + erff(v * 0.70710678118654752f));
}
__device__ __forceinline__ uint32_t cvt_tf32(float f) {
    uint32_t u;
    asm("cvt.rna.tf32.f32 %0, %1;" : "=r"(u) : "f"(f));
    return u;
}
__device__ __forceinline__ float tf32r(float f) { return __uint_as_float(cvt_tf32(f)); }

__device__ __forceinline__ float blk_sum128(float v, float* red) {
    int lane = threadIdx.x & 31, wid = threadIdx.x >> 5;
#pragma unroll
    for (int o = 16; o; o >>= 1) v += __shfl_xor_sync(0xffffffffu, v, o);
    if (lane == 0) red[wid] = v;
    __syncthreads();
    float t = (lane < 4) ? red[lane] : 0.0f;
#pragma unroll
    for (int o = 2; o; o >>= 1) t += __shfl_xor_sync(0xffffffffu, t, o);
    t = __shfl_sync(0xffffffffu, t, 0);
    __syncthreads();
    return t;
}

// ---------------- weight pre-round to tf32 (vectorized) ----------------
__global__ void round_weights(const float* __restrict__ a, const float* __restrict__ b,
                              const float* __restrict__ c, const float* __restrict__ d,
                              float* __restrict__ o) {
    int i = (blockIdx.x * 256 + threadIdx.x) * 4;
    const int n1 = W_QKV_E, n2 = n1 + W_ATT_E, n3 = n2 + W_FC1_E, n4 = n3 + W_FC2_E;
    if (i >= n4) return;
    const float* src;
    int off;
    if (i < n1)      { src = a; off = i; }
    else if (i < n2) { src = b; off = i - n1; }
    else if (i < n3) { src = c; off = i - n2; }
    else             { src = d; off = i - n3; }
    float4 v = *(const float4*)(src + off);
    v.x = tf32r(v.x); v.y = tf32r(v.y); v.z = tf32r(v.z); v.w = tf32r(v.w);
    *(float4*)(o + i) = v;
}

// ---------------- LN + roll + window partition (output tf32-rounded: feeds GEMM A) ----------------
__global__ void ln_win_kernel(const float* __restrict__ x, const float* __restrict__ gam,
                              const float* __restrict__ bet, float* __restrict__ out) {
    __shared__ float red[32];
    int row = blockIdx.x;
    int b2 = row / LW, l = row - b2 * LW;
    int b = b2 >> 6, w = b2 & 63;
    int r = (w >> 3) * WSZ + l / WSZ;
    int c = (w & 7) * WSZ + l % WSZ;
    int r0 = (r + SSH) % HIMG;
    int c0 = (c + SSH) % HIMG;
    const float* xin = x + ((size_t)b * LSEQ + r0 * HIMG + c0) * DIM;
    int tid = threadIdx.x;
    float v0 = xin[tid], v1 = xin[tid + 128], v2 = xin[tid + 256];
    float mu = blk_sum128(v0 + v1 + v2, red) * (1.0f / (float)DIM);
    float d0 = v0 - mu, d1 = v1 - mu, d2 = v2 - mu;
    float var = blk_sum128(d0 * d0 + d1 * d1 + d2 * d2, red) * (1.0f / (float)DIM);
    float inv = rsqrtf(var + 1e-3f);
    float* o = out + (size_t)row * DIM;
    o[tid]       = tf32r(d0 * inv * gam[tid]       + bet[tid]);
    o[tid + 128] = tf32r(d1 * inv * gam[tid + 128] + bet[tid + 128]);
    o[tid + 256] = tf32r(d2 * inv * gam[tid + 256] + bet[tid + 256]);
}

// ---------------- fused: x2 = x + window_reverse(unshift(proj));  hw = tf32(LN(x2)) ----------------
__global__ void res_ln_kernel(const float* __restrict__ x, const float* __restrict__ proj,
                              const float* __restrict__ gam, const float* __restrict__ bet,
                              float* __restrict__ x2, float* __restrict__ hw) {
    __shared__ float red[32];
    int pix = blockIdx.x;
    int b = pix / LSEQ, p = pix - b * LSEQ;
    int r0 = p / HIMG, c0 = p - r0 * HIMG;
    int r = (r0 + HIMG - SSH) % HIMG;
    int c = (c0 + HIMG - SSH) % HIMG;
    int row_in = (b * NWIN + (r / WSZ) * 8 + (c / WSZ)) * LW + (r % WSZ) * WSZ + (c % WSZ);
    const float* xp = x + (size_t)pix * DIM;
    const float* pp = proj + (size_t)row_in * DIM;
    int tid = threadIdx.x;
    float v0 = xp[tid] + pp[tid];
    float v1 = xp[tid + 128] + pp[tid + 128];
    float v2 = xp[tid + 256] + pp[tid + 256];
    float* xo = x2 + (size_t)pix * DIM;
    xo[tid] = v0; xo[tid + 128] = v1; xo[tid + 256] = v2;
    float mu = blk_sum128(v0 + v1 + v2, red) * (1.0f / (float)DIM);
    float d0 = v0 - mu, d1 = v1 - mu, d2 = v2 - mu;
    float var = blk_sum128(d0 * d0 + d1 * d1 + d2 * d2, red) * (1.0f / (float)DIM);
    float inv = rsqrtf(var + 1e-3f);
    float* o = hw + (size_t)pix * DIM;
    o[tid]       = tf32r(d0 * inv * gam[tid]       + bet[tid]);
    o[tid + 128] = tf32r(d1 * inv * gam[tid + 128] + bet[tid + 128]);
    o[tid + 256] = tf32r(d2 * inv * gam[tid + 256] + bet[tid + 256]);
}

// ================= TF32 tensor-core GEMM =================
// Operands are PRE-ROUNDED to tf32 (bit pattern) — no cvt in the inner loop.
// EPI 0: gelu, store C[M,N].  EPI 1: + res, store C[M,N].
// EPI 2: gelu, store TRANSPOSED C_T[N][M] (smem-staged, coalesced).
// RND: tf32-round stored output (EPI 0/1 path only).
#define BMT 128
#define BNT 128
#define BKT 32
#define ASTR 36
#define BSTR 136
#define AS_ELEMS (BMT*ASTR)   // 4608 floats
#define BS_ELEMS (BKT*BSTR)   // 4352 floats
#define GEMM_SMEM ((2*AS_ELEMS + 2*BS_ELEMS)*4)  // 71680 B  (>= 128*132*4 = 67584 for EPI2 staging)

__device__ __forceinline__ void cp_async16(uint32_t saddr, const float* g) {
    asm volatile("cp.async.cg.shared.global [%0], [%1], 16;\n" :: "r"(saddr), "l"(g));
}

template <int EPI, bool RND>
__global__ void __launch_bounds__(256, 2)
tf32gemm_kernel(const float* __restrict__ A, const float* __restrict__ Bm,
                const float* __restrict__ bias, const float* __restrict__ res,
                float* __restrict__ C, int M, int N, int K) {
    extern __shared__ float sm[];
    float* As = sm;                    // [2][128][36]
    float* Bs = sm + 2 * AS_ELEMS;     // [2][32][136]

    const int t = threadIdx.x;
    const int bm = blockIdx.y * BMT, bn = blockIdx.x * BNT;
    const int lane = t & 31, wid = t >> 5;
    const int wm = (wid & 1) * 64;
    const int wn = (wid >> 1) * 32;
    const int gid = lane >> 2, tig = lane & 3;

    const float* aptr[4];
    uint32_t asm_addr[4];
    uint32_t smem_base = (uint32_t)__cvta_generic_to_shared(sm);
#pragma unroll
    for (int i = 0; i < 4; i++) {
        int flat = (i * 256 + t) * 4;
        int arow = flat >> 5, akk = flat & 31;
        aptr[i] = A + (size_t)(bm + arow) * K + akk;
        asm_addr[i] = smem_base + (arow * ASTR + akk) * 4;
    }
    const float* bptr[4];
    uint32_t bsm_addr[4];
#pragma unroll
    for (int i = 0; i < 4; i++) {
        int flat = (i * 256 + t) * 4;
        int bkk = flat >> 7, bno = flat & 127;
        bptr[i] = Bm + (size_t)bkk * N + bn + bno;
        bsm_addr[i] = smem_base + (2 * AS_ELEMS + bkk * BSTR + bno) * 4;
    }

    float acc[4][4][4];
#pragma unroll
    for (int a = 0; a < 4; a++)
#pragma unroll
        for (int b = 0; b < 4; b++)
#pragma unroll
            for (int c = 0; c < 4; c++) acc[a][b][c] = 0.0f;

    const int NIT = K / BKT;
#pragma unroll
    for (int i = 0; i < 4; i++) cp_async16(asm_addr[i], aptr[i]);
#pragma unroll
    for (int i = 0; i < 4; i++) cp_async16(bsm_addr[i], bptr[i]);
    asm volatile("cp.async.commit_group;\n");

    for (int it = 0; it < NIT; ++it) {
        const int cur = it & 1;
        if (it + 1 < NIT) {
            const int nb = cur ^ 1;
            const int k0 = (it + 1) * BKT;
#pragma unroll
            for (int i = 0; i < 4; i++)
                cp_async16(asm_addr[i] + nb * AS_ELEMS * 4, aptr[i] + k0);
#pragma unroll
            for (int i = 0; i < 4; i++)
                cp_async16(bsm_addr[i] + nb * BS_ELEMS * 4, bptr[i] + (size_t)k0 * N);
        }
        asm volatile("cp.async.commit_group;\n");
        asm volatile("cp.async.wait_group 1;\n");
        __syncthreads();

        const uint32_t* Ac = (const uint32_t*)(As + cur * AS_ELEMS);
        const uint32_t* Bc = (const uint32_t*)(Bs + cur * BS_ELEMS);
#pragma unroll
        for (int k8 = 0; k8 < BKT; k8 += 8) {
            uint32_t ua[4][4], ub[4][2];
#pragma unroll
            for (int mt = 0; mt < 4; mt++) {
                int r = wm + mt * 16 + gid;
                ua[mt][0] = Ac[(r)     * ASTR + k8 + tig];
                ua[mt][1] = Ac[(r + 8) * ASTR + k8 + tig];
                ua[mt][2] = Ac[(r)     * ASTR + k8 + tig + 4];
                ua[mt][3] = Ac[(r + 8) * ASTR + k8 + tig + 4];
            }
#pragma unroll
            for (int nt = 0; nt < 4; nt++) {
                int ncol = wn + nt * 8 + gid;
                ub[nt][0] = Bc[(k8 + tig)     * BSTR + ncol];
                ub[nt][1] = Bc[(k8 + tig + 4) * BSTR + ncol];
            }
#pragma unroll
            for (int mt = 0; mt < 4; mt++)
#pragma unroll
                for (int nt = 0; nt < 4; nt++) {
                    asm volatile(
                        "mma.sync.aligned.m16n8k8.row.col.f32.tf32.tf32.f32 "
                        "{%0,%1,%2,%3}, {%4,%5,%6,%7}, {%8,%9}, {%0,%1,%2,%3};"
                        : "+f"(acc[mt][nt][0]), "+f"(acc[mt][nt][1]),
                          "+f"(acc[mt][nt][2]), "+f"(acc[mt][nt][3])
                        : "r"(ua[mt][0]), "r"(ua[mt][1]), "r"(ua[mt][2]), "r"(ua[mt][3]),
                          "r"(ub[nt][0]), "r"(ub[nt][1]));
                }
        }
        __syncthreads();
    }

    // ---- epilogue ----
    if (EPI == 2) {
        float* st = sm;   // mainloop smem fully consumed
#pragma unroll
        for (int mt = 0; mt < 4; mt++) {
            int r0 = wm + mt * 16 + gid;
#pragma unroll
            for (int nt = 0; nt < 4; nt++) {
                int c0 = wn + nt * 8 + 2 * tig;
                float bia0 = bias[bn + c0], bia1 = bias[bn + c0 + 1];
                float v00 = gelu_f(acc[mt][nt][0] + bia0);
                float v01 = gelu_f(acc[mt][nt][1] + bia1);
                float v10 = gelu_f(acc[mt][nt][2] + bia0);
                float v11 = gelu_f(acc[mt][nt][3] + bia1);
                st[(c0)     * 132 + r0]     = v00;
                st[(c0 + 1) * 132 + r0]     = v01;
                st[(c0)     * 132 + r0 + 8] = v10;
                st[(c0 + 1) * 132 + r0 + 8] = v11;
            }
        }
        __syncthreads();
#pragma unroll
        for (int rep = 0; rep < 4; rep++) {
            int n = rep * 32 + (t >> 3);
            int mb = (t & 7) * 4;
#pragma unroll
            for (int k = 0; k < 4; k++) {
                int m = mb + 32 * k;
                float4 v = *(float4*)&st[n * 132 + m];
                *(float4*)(C + (size_t)(bn + n) * M + bm + m) = v;
            }
        }
    } else {
#pragma unroll
        for (int mt = 0; mt < 4; mt++) {
            int r0 = bm + wm + mt * 16 + gid;
#pragma unroll
            for (int nt = 0; nt < 4; nt++) {
                int c0 = bn + wn + nt * 8 + 2 * tig;
                float bia0 = bias[c0], bia1 = bias[c0 + 1];
                float v00 = acc[mt][nt][0] + bia0, v01 = acc[mt][nt][1] + bia1;
                float v10 = acc[mt][nt][2] + bia0, v11 = acc[mt][nt][3] + bia1;
                if (EPI == 0) {
                    v00 = gelu_f(v00); v01 = gelu_f(v01);
                    v10 = gelu_f(v10); v11 = gelu_f(v11);
                } else {
                    const float* rp0 = res + (size_t)r0 * N + c0;
                    const float* rp1 = res + (size_t)(r0 + 8) * N + c0;
                    v00 += rp0[0]; v01 += rp0[1];
                    v10 += rp1[0]; v11 += rp1[1];
                }
                if (RND) {
                    v00 = tf32r(v00); v01 = tf32r(v01);
                    v10 = tf32r(v10); v11 = tf32r(v11);
                }
                float2* o0 = (float2*)(C + (size_t)r0 * N + c0);
                float2* o1 = (float2*)(C + (size_t)(r0 + 8) * N + c0);
                *o0 = make_float2(v00, v01);
                *o1 = make_float2(v10, v11);
            }
        }
    }
}

// ---------------- per-(window-batch, head) attention ----------------
// qkvT layout: [DIM3][MROWS] -> gather is 3 contiguous 6KB streams per block.
// K is stored TRANSPOSED in smem (ks_t[e][m], row stride 51) so the score loop's
// per-lane addresses are consecutive -> conflict-free (was 32-way conflicted).
__global__ void attn_kernel(const float* __restrict__ qkvT,
                            const float* __restrict__ bias_table,
                            float* __restrict__ att) {
    int b2 = blockIdx.x;
    int h2 = blockIdx.y;
    __shared__ float qs[LW * HD], vs[LW * HD];
    __shared__ float ks_t[HD * KSTR];          // [e][m], stride 51
    __shared__ float sc[LW][LW + 1];
    __shared__ int   rid[LW];
    int tid = threadIdx.x;   // 128
    int lane = tid & 31, wid = tid >> 5;

    int fbase = b2 * (HEADS * LW * HD) + h2 * (LW * HD);
    int cc  = fbase / MROWS;
    int off = fbase - cc * MROWS;
    const float* qrow = qkvT + (size_t)(cc)           * MROWS + off;
    const float* krow = qkvT + (size_t)(cc + DIM)     * MROWS + off;
    const float* vrow = qkvT + (size_t)(cc + 2 * DIM) * MROWS + off;
    for (int idx = tid; idx < LW * HD; idx += 128) {
        int l = idx >> 5, e = idx & 31;        // HD == 32
        qs[idx] = qrow[idx];
        vs[idx] = vrow[idx];
        ks_t[e * KSTR + l] = krow[idx];        // transpose: write stride 51 (odd) -> all banks
    }
    if (tid < LW) {
        int w = b2 & 63;
        int r = (w >> 3) * WSZ + tid / WSZ;
        int c = (w & 7) * WSZ + tid % WSZ;
        int gr = (r < 7) ? 0 : (r < 10) ? 1 : (r >= 53) ? 2 : -1;
        int gc = (c < 7) ? 0 : (c < 10) ? 1 : (c >= 53) ? 2 : -1;
        rid[tid] = (gr < 0 || gc < 0) ? 0 : gr * 3 + gc;
    }
    __syncthreads();

    // scores: lane-consecutive m -> ks_t reads consecutive, qs broadcast
    for (int idx = tid; idx < LW * LW; idx += 128) {
        int l = idx / LW, m = idx - l * LW;
        float s = 0.0f;
#pragma unroll
        for (int e = 0; e < HD; e++) s += qs[l * HD + e] * ks_t[e * KSTR + m];
        int ri = 13 * ((m % 7 - l % 7) + (m / 7 - l / 7) + 12);
        s += bias_table[ri * HEADS + h2];
        if (rid[l] != rid[m]) s -= 100.0f;
        sc[l][m] = s;
    }
    __syncthreads();

    // warp-parallel softmax: each warp owns rows l = wid, wid+4, ...
    for (int l = wid; l < LW; l += 4) {
        float a = (lane < LW) ? sc[l][lane] : -1e30f;
        float b = (lane + 32 < LW) ? sc[l][lane + 32] : -1e30f;
        float mx = fmaxf(a, b);
#pragma unroll
        for (int o = 16; o; o >>= 1) mx = fmaxf(mx, __shfl_xor_sync(0xffffffffu, mx, o));
        float e0 = (lane < LW) ? expf(a - mx) : 0.0f;
        float e1 = (lane + 32 < LW) ? expf(b - mx) : 0.0f;
        float s = e0 + e1;
#pragma unroll
        for (int o = 16; o; o >>= 1) s += __shfl_xor_sync(0xffffffffu, s, o);
        float inv = 1.0f / s;
        if (lane < LW) sc[l][lane] = e0 * inv;
        if (lane + 32 < LW) sc[l][lane + 32] = e1 * inv;
    }
    __syncthreads();

    // out = attn @ v : lane varies e -> vs consecutive, sc broadcast
    for (int idx = tid; idx < LW * HD; idx += 128) {
        int l = idx / HD, e = idx - l * HD;
        float o = 0.0f;
#pragma unroll 7
        for (int m = 0; m < LW; m++) o += sc[l][m] * vs[m * HD + e];
        att[(size_t)(b2 * LW + l) * DIM + h2 * HD + e] = tf32r(o);
    }
}

// ---------------- launch ----------------
extern "C" void kernel_launch(void* const* d_in, const int* in_sizes, int n_in,
                              void* d_out, int out_size) {
    const float* x          = (const float*)d_in[0];
    const float* gamma      = (const float*)d_in[1];
    const float* beta       = (const float*)d_in[2];
    const float* w_qkv      = (const float*)d_in[3];
    const float* b_qkv      = (const float*)d_in[4];
    const float* bias_table = (const float*)d_in[5];
    const float* w_att      = (const float*)d_in[6];
    const float* b_att      = (const float*)d_in[7];
    const float* w_fc1      = (const float*)d_in[8];
    const float* b_fc1      = (const float*)d_in[9];
    const float* w_fc2      = (const float*)d_in[10];
    const float* b_fc2      = (const float*)d_in[11];
    float* out = (float*)d_out;

    float *hw, *qkv, *att, *proj, *x2, *f1, *wt;
    cudaGetSymbolAddress((void**)&hw,   g_hw);
    cudaGetSymbolAddress((void**)&qkv,  g_qkv);
    cudaGetSymbolAddress((void**)&att,  g_att);
    cudaGetSymbolAddress((void**)&proj, g_proj);
    cudaGetSymbolAddress((void**)&x2,   g_x2);
    cudaGetSymbolAddress((void**)&f1,   g_f1);
    cudaGetSymbolAddress((void**)&wt,   g_wt);

    const float* wq = wt;
    const float* wa = wt + W_QKV_E;
    const float* w1 = wt + W_QKV_E + W_ATT_E;
    const float* w2 = wt + W_QKV_E + W_ATT_E + W_FC1_E;

    cudaFuncSetAttribute(tf32gemm_kernel<0, false>, cudaFuncAttributeMaxDynamicSharedMemorySize, GEMM_SMEM);
    cudaFuncSetAttribute(tf32gemm_kernel<0, true>,  cudaFuncAttributeMaxDynamicSharedMemorySize, GEMM_SMEM);
    cudaFuncSetAttribute(tf32gemm_kernel<1, false>, cudaFuncAttributeMaxDynamicSharedMemorySize, GEMM_SMEM);
    cudaFuncSetAttribute(tf32gemm_kernel<2, false>, cudaFuncAttributeMaxDynamicSharedMemorySize, GEMM_SMEM);

    // 0. tf32-round all weights once per call
    {
        int total = W_QKV_E + W_ATT_E + W_FC1_E + W_FC2_E;
        round_weights<<<(total / 4 + 255) / 256, 256>>>(w_qkv, w_att, w_fc1, w_fc2, wt);
    }
    // 1. hw = tf32(LN(roll+window(x)))
    ln_win_kernel<<<MROWS, 128>>>(x, gamma, beta, hw);
    // 2. qkvT = gelu(hw @ wq + b_qkv), stored TRANSPOSED [DIM3][MROWS]
    tf32gemm_kernel<2, false><<<dim3(DIM3 / BNT, MROWS / BMT), 256, GEMM_SMEM>>>(hw, wq, b_qkv, nullptr, qkv, MROWS, DIM3, DIM);
    // 3. att = tf32(windowed attention), coalesced gather + conflict-free smem
    attn_kernel<<<dim3(BNW, HEADS), 128>>>(qkv, bias_table, att);
    // 4. proj = gelu(att @ wa + b_att)
    tf32gemm_kernel<0, false><<<dim3(DIM / BNT, MROWS / BMT), 256, GEMM_SMEM>>>(att, wa, b_att, nullptr, proj, MROWS, DIM, DIM);
    // 5+6. x2 = x + reverse(proj); hw = tf32(LN(x2))
    res_ln_kernel<<<BATCH * LSEQ, 128>>>(x, proj, gamma, beta, x2, hw);
    // 7. f1 = tf32(gelu(hw @ w1 + b_fc1))
    tf32gemm_kernel<0, true><<<dim3(DFF / BNT, MROWS / BMT), 256, GEMM_SMEM>>>(hw, w1, b_fc1, nullptr, f1, MROWS, DFF, DIM);
    // 8. out = x2 + f1 @ w2 + b_fc2
    tf32gemm_kernel<1, false><<<dim3(DIM / BNT, MROWS / BMT), 256, GEMM_SMEM>>>(f1, w2, b_fc2, x2, out, MROWS, DIM, DFF);
}